// round 5
// baseline (speedup 1.0000x reference)
#include <cuda_runtime.h>
#include <math.h>

#define Bx 8
#define Nx 512
#define Dx 128
#define Hx 64
#define FNx 3
#define NLx 3
#define OUTC 10
#define BN (Bx*Nx)

// ---------------- device scratch (static, no allocation) ----------------
__device__ float    g_kap[BN];
__device__ float    g_f[FNx][BN];
__device__ float    g_m1;
__device__ unsigned g_adj[BN*16];       // 512-bit row bitmask per node
__device__ unsigned g_kmask1[Bx*16];    // keep bitmask after prune 1
__device__ unsigned g_kmask2[Bx*16];    // cumulative keep after prune 2
__device__ float    g_batchloss[Bx];
__device__ float    g_h[NLx][BN*Hx];
__device__ float    g_part[Bx*8*320];

// ---------------- kernel 1: compress binary A to bitmasks ----------------
// grid 512 blocks x 256 threads; warp per row
__global__ void adjmask_kernel(const float* __restrict__ A)
{
    int w = threadIdx.x >> 5, lane = threadIdx.x & 31;
    int r = blockIdx.x * 8 + w;
    const float* Ar = A + (size_t)r * Nx;
    unsigned myword = 0;
    #pragma unroll
    for (int c = 0; c < 16; c++) {
        float v = Ar[c*32 + lane];
        unsigned m = __ballot_sync(0xffffffffu, v != 0.f);
        if (lane == c) myword = m;
    }
    if (lane < 16) g_adj[(size_t)r*16 + lane] = myword;
}

// ---------------- kernel 2: node MLPs (curv + 3 fn), tiled; m1 as slice 4 --
// grid (BN/32, 5), 256 threads, dynamic smem 57600 B
__global__ void node_mlps_tiled(const float* __restrict__ X,
    const float* __restrict__ cW1, const float* __restrict__ cb1,
    const float* __restrict__ cW2, const float* __restrict__ cb2,
    const float* __restrict__ fW1, const float* __restrict__ fb1,
    const float* __restrict__ fW2, const float* __restrict__ fb2,
    const float* __restrict__ wmW1, const float* __restrict__ wmb1,
    const float* __restrict__ wmW2, const float* __restrict__ wmb2,
    const float* __restrict__ wmW3, const float* __restrict__ wmb3)
{
    extern __shared__ float sm[];
    int tid = threadIdx.x;
    int m = blockIdx.y;

    if (m == 4) {   // scalar m1 = sigmoid(MLP(1)) — only block 0 of this slice
        if (blockIdx.x != 0) return;
        float* s1 = sm;        // 64
        float* s2 = sm + 64;   // 32
        if (tid < 64) s1[tid] = fmaxf(wmW1[tid] + wmb1[tid], 0.f);
        __syncthreads();
        if (tid < 32) {
            float a = wmb2[tid];
            #pragma unroll
            for (int i = 0; i < 64; i++) a += s1[i] * wmW2[i*32 + tid];
            s2[tid] = fmaxf(a, 0.f);
        }
        __syncthreads();
        if (tid == 0) {
            float s = wmb3[0];
            #pragma unroll
            for (int i = 0; i < 32; i++) s += s2[i] * wmW3[i];
            g_m1 = 1.f / (1.f + expf(-s));
        }
        return;
    }

    float* sX   = sm;                    // 32*128 = 4096
    float* sW1  = sm + 4096;             // 128*64 = 8192
    float* sHid = sm + 4096 + 8192;      // 32*64  = 2048
    float* sW2v = sHid + 2048;           // 64
    int nodeBase = blockIdx.x * 32;

    const float* W1 = (m == 0) ? cW1 : fW1 + (size_t)(m-1)*Dx*Hx;
    const float* B1 = (m == 0) ? cb1 : fb1 + (m-1)*Hx;
    const float* W2 = (m == 0) ? cW2 : fW2 + (m-1)*Hx;
    float B2 = (m == 0) ? cb2[0] : fb2[m-1];

    for (int i = tid; i < 32*Dx; i += 256) sX[i] = X[(size_t)nodeBase*Dx + i];
    for (int i = tid; i < Dx*Hx; i += 256) sW1[i] = W1[i];
    if (tid < 64) sW2v[tid] = W2[tid];
    __syncthreads();

    // hidden: thread owns 2 h-cols x 4 nodes
    {
        int h2 = tid & 31, g8 = tid >> 5;
        float r[4][2];
        float b1a = B1[2*h2], b1b = B1[2*h2+1];
        #pragma unroll
        for (int k = 0; k < 4; k++) { r[k][0] = b1a; r[k][1] = b1b; }
        for (int d = 0; d < Dx; d++) {
            float2 wv = *(const float2*)&sW1[d*64 + 2*h2];
            #pragma unroll
            for (int k = 0; k < 4; k++) {
                float a = sX[(g8 + 8*k)*Dx + d];
                r[k][0] += a * wv.x; r[k][1] += a * wv.y;
            }
        }
        #pragma unroll
        for (int k = 0; k < 4; k++) {
            float2 o; o.x = fmaxf(r[k][0], 0.f); o.y = fmaxf(r[k][1], 0.f);
            *(float2*)&sHid[(g8 + 8*k)*64 + 2*h2] = o;
        }
    }
    __syncthreads();

    // scalar head: warp per node (4 rounds)
    int w = tid >> 5, lane = tid & 31;
    for (int nn = 0; nn < 4; nn++) {
        int nl = w*4 + nn;
        float v = sHid[nl*64 + lane] * sW2v[lane]
                + sHid[nl*64 + 32 + lane] * sW2v[32 + lane];
        #pragma unroll
        for (int o = 16; o > 0; o >>= 1) v += __shfl_xor_sync(0xffffffffu, v, o);
        if (lane == 0) {
            float s = v + B2;
            float sig = 1.f / (1.f + expf(-s));
            int node = nodeBase + nl;
            if (m == 0) g_kap[node] = sig; else g_f[m-1][node] = sig;
        }
    }
}

// ---------------- kernel 3: top-k prune -> keep bitmasks (exact jax ties) --
// grid = B blocks, 512 threads
__global__ void prune_kernel(const int* __restrict__ p_ptr)
{
    __shared__ float sv[Nx];
    __shared__ float so[Nx];
    int b = blockIdx.x, t = threadIdx.x;
    float v = g_kap[b*Nx + t];
    so[t] = v; sv[t] = v;
    __syncthreads();
    for (int k = 2; k <= Nx; k <<= 1) {
      for (int j = k >> 1; j > 0; j >>= 1) {
        int ixj = t ^ j;
        if (ixj > t) {
          float a = sv[t], c = sv[ixj];
          bool up = ((t & k) == 0);
          if ((a > c) == up) { sv[t] = c; sv[ixj] = a; }
        }
        __syncthreads();
      }
    }
    int p = *p_ptr;
    float keepA = 1.f, keepB = 1.f;
    for (int phase = 0; phase < 2; phase++) {
        int k = (Nx * p * (phase+1)) / 100;
        bool removed = false;
        if (k >= 1) {
            float T = sv[Nx - k];
            int isgt = (so[t] > T) ? 1 : 0;
            int cgt = __syncthreads_count(isgt);
            int need = k - cgt;
            removed = (so[t] > T);
            if (!removed && so[t] == T && need > 0) {
                int r = 0;
                for (int j = 0; j < t; j++) if (so[j] == T) r++;
                if (r < need) removed = true;
            }
        }
        if (phase == 0) keepA = removed ? 0.f : 1.f; else keepB = removed ? 0.f : 1.f;
        __syncthreads();
    }
    unsigned m1b = __ballot_sync(0xffffffffu, keepA != 0.f);
    unsigned m2b = __ballot_sync(0xffffffffu, keepA * keepB != 0.f);
    if ((t & 31) == 0) {
        g_kmask1[b*16 + (t >> 5)] = m1b;
        g_kmask2[b*16 + (t >> 5)] = m2b;
    }
}

// ---------------- kernel 4: fused curvature (both passes + loss per batch) -
// grid = Bx blocks, 512 threads (thread per row)
__global__ void curv_kernel()
{
    __shared__ float  sf[FNx][Nx];
    __shared__ float4 sg[FNx][Nx];   // (gamma, df, f*df, -)
    __shared__ float  red[Nx];
    int b = blockIdx.x, t = threadIdx.x;
    int idx = b*Nx + t;
    #pragma unroll
    for (int i = 0; i < FNx; i++) sf[i][t] = g_f[i][idx];
    unsigned wrd[16];
    #pragma unroll
    for (int c = 0; c < 16; c++) wrd[c] = g_adj[(size_t)idx*16 + c];
    __syncthreads();

    float m1 = g_m1;
    int degi = 0;
    #pragma unroll
    for (int c = 0; c < 16; c++) degi += __popc(wrd[c]);
    float deg = (float)degi;

    float u1[FNx] = {0,0,0}, u2[FNx] = {0,0,0};
    #pragma unroll
    for (int c = 0; c < 16; c++) {
        unsigned bits = wrd[c];
        while (bits) {
            int j = c*32 + __ffs(bits) - 1; bits &= bits - 1;
            #pragma unroll
            for (int i = 0; i < FNx; i++) { float fv = sf[i][j]; u1[i] += fv; u2[i] += fv*fv; }
        }
    }
    #pragma unroll
    for (int i = 0; i < FNx; i++) {
        float fr = sf[i][t];
        float gam = 0.5f*m1*(fr*fr*deg - 2.f*fr*u1[i] + u2[i]);
        float df  = m1*(fr*deg - u1[i]);
        sg[i][t] = make_float4(gam, df, fr*df, 0.f);
    }
    __syncthreads();

    float v1[FNx] = {0,0,0}, v2[FNx] = {0,0,0}, v3[FNx] = {0,0,0};
    #pragma unroll
    for (int c = 0; c < 16; c++) {
        unsigned bits = wrd[c];
        while (bits) {
            int j = c*32 + __ffs(bits) - 1; bits &= bits - 1;
            #pragma unroll
            for (int i = 0; i < FNx; i++) {
                float4 g = sg[i][j];
                v1[i] += g.x; v2[i] += g.y; v3[i] += g.z;
            }
        }
    }
    float kap = g_kap[idx], term = 0.f;
    #pragma unroll
    for (int i = 0; i < FNx; i++) {
        float4 own = sg[i][t]; float fr = sf[i][t];
        float dgam = m1*(own.x*deg - v1[i]);
        float gfd  = 0.5f*m1*(own.z*deg - fr*v2[i] - own.y*u1[i] + v3[i]);
        float g2 = 0.5f*dgam - gfd;
        term += fmaxf(kap*own.x - g2, 0.f);
    }
    red[t] = term - 3.f*kap;
    __syncthreads();
    for (int o = 256; o > 0; o >>= 1) { if (t < o) red[t] += red[t + o]; __syncthreads(); }
    if (t == 0) g_batchloss[b] = red[0];
}

// ---------------- kernel 5: fused sparse-aggregation + GIN 2-layer MLP -----
// grid = 128 blocks, 256 threads, dynamic smem
template<int DIN>
__global__ void gin_kernel(const float* __restrict__ hin,
    const unsigned* __restrict__ kmask,
    const float* __restrict__ eps_ptr, int t_idx,
    const float* __restrict__ W1, const float* __restrict__ b1,
    const float* __restrict__ W2, const float* __restrict__ b2,
    float* __restrict__ hout)
{
    extern __shared__ float sm2[];
    float* sW1  = sm2;                    // DIN*64
    float* sW2  = sW1 + DIN*64;           // 64*64
    float* sAgg = sW2 + 64*64;            // 32*DIN
    float* sHid = sAgg + 32*DIN;          // 32*64
    const int tid = threadIdx.x;
    const int nodeBase = blockIdx.x * 32;
    const int b = nodeBase >> 9;

    for (int i = tid; i < DIN*64; i += 256) sW1[i] = W1[i];
    for (int i = tid; i < 64*64; i += 256)  sW2[i] = W2[i];

    const int w = tid >> 5, lane = tid & 31;
    const float eps1 = 1.f + eps_ptr[t_idx];
    const unsigned full = 0xffffffffu;

    for (int nn = 0; nn < 4; nn++) {
        int nl = w*4 + nn;
        int node = nodeBase + nl;
        unsigned myw = 0;
        if (lane < 16) {
            myw = g_adj[(size_t)node*16 + lane];
            if (kmask) myw &= kmask[b*16 + lane];
        }
        bool rk = true;
        if (kmask) rk = (kmask[b*16 + ((node & 511) >> 5)] >> (node & 31)) & 1u;
        float acc[DIN/32];
        #pragma unroll
        for (int q = 0; q < DIN/32; q++) acc[q] = 0.f;
        if (rk) {
            #pragma unroll 1
            for (int c = 0; c < 16; c++) {
                unsigned bits = __shfl_sync(full, myw, c);
                while (bits) {
                    int j = __ffs(bits) - 1; bits &= bits - 1;
                    const float* hr = hin + ((size_t)(b*Nx + c*32 + j))*DIN;
                    #pragma unroll
                    for (int q = 0; q < DIN/32; q++) acc[q] += hr[lane + 32*q];
                }
            }
        }
        const float* hs = hin + (size_t)node*DIN;
        #pragma unroll
        for (int q = 0; q < DIN/32; q++)
            sAgg[nl*DIN + lane + 32*q] = eps1*hs[lane + 32*q] + acc[q];
    }
    __syncthreads();

    // hidden layer: thread owns 2 cols x 4 nodes
    {
        int h2 = tid & 31, g8 = tid >> 5;
        float r[4][2];
        float b1a = b1[2*h2], b1b = b1[2*h2+1];
        #pragma unroll
        for (int k = 0; k < 4; k++) { r[k][0] = b1a; r[k][1] = b1b; }
        for (int d = 0; d < DIN; d++) {
            float2 wv = *(const float2*)&sW1[d*64 + 2*h2];
            #pragma unroll
            for (int k = 0; k < 4; k++) {
                float a = sAgg[(g8 + 8*k)*DIN + d];
                r[k][0] += a * wv.x; r[k][1] += a * wv.y;
            }
        }
        #pragma unroll
        for (int k = 0; k < 4; k++) {
            float2 o; o.x = fmaxf(r[k][0], 0.f); o.y = fmaxf(r[k][1], 0.f);
            *(float2*)&sHid[(g8 + 8*k)*64 + 2*h2] = o;
        }
    }
    __syncthreads();

    // output layer
    {
        int h2 = tid & 31, g8 = tid >> 5;
        float r[4][2];
        float b2a = b2[2*h2], b2b = b2[2*h2+1];
        #pragma unroll
        for (int k = 0; k < 4; k++) { r[k][0] = b2a; r[k][1] = b2b; }
        for (int d = 0; d < 64; d++) {
            float2 wv = *(const float2*)&sW2[d*64 + 2*h2];
            #pragma unroll
            for (int k = 0; k < 4; k++) {
                float a = sHid[(g8 + 8*k)*64 + d];
                r[k][0] += a * wv.x; r[k][1] += a * wv.y;
            }
        }
        #pragma unroll
        for (int k = 0; k < 4; k++) {
            float2 o; o.x = fmaxf(r[k][0], 0.f); o.y = fmaxf(r[k][1], 0.f);
            *(float2*)&hout[((size_t)(nodeBase + g8 + 8*k))*64 + 2*h2] = o;
        }
    }
}

// ---------------- kernel 6: readout stage 1 (partial column sums) ----------
// grid (Bx, 8), 320 threads
__global__ void final_part_kernel(const float* __restrict__ X)
{
    int b = blockIdx.x, pp = blockIdx.y, t = threadIdx.x;
    int n0 = pp * 64;
    float a = 0.f;
    if (t < 128) {
        for (int n = n0; n < n0 + 64; n++) a += X[((size_t)(b*Nx + n))*Dx + t];
    } else {
        int layer = (t - 128) >> 6, c = (t - 128) & 63;
        const float* H = &g_h[layer][0];
        for (int n = n0; n < n0 + 64; n++) a += H[(b*Nx + n)*Hx + c];
    }
    g_part[(b*8 + pp)*320 + t] = a;
}

// ---------------- kernel 7: readout stage 2 (matmul + loss write) ----------
// grid = Bx, 320 threads
__global__ void final_out_kernel(const float* __restrict__ outW,
                                 const float* __restrict__ outb,
                                 float* __restrict__ dout, int out_size)
{
    __shared__ float S[320];
    int b = blockIdx.x, t = threadIdx.x;
    float a = 0.f;
    #pragma unroll
    for (int p2 = 0; p2 < 8; p2++) a += g_part[(b*8 + p2)*320 + t];
    S[t] = a;
    __syncthreads();
    if (t < OUTC) {
        float o = outb[t];
        for (int f = 0; f < 320; f++) o += S[f] * outW[f*OUTC + t];
        dout[b*OUTC + t] = o;
    }
    if (b == 0 && t == OUTC && out_size > Bx*OUTC) {
        float l = 0.f;
        #pragma unroll
        for (int i = 0; i < Bx; i++) l += g_batchloss[i];
        dout[Bx*OUTC] = l;
    }
}

// ---------------- launch ----------------
extern "C" void kernel_launch(void* const* d_in, const int* in_sizes, int n_in,
                              void* d_out, int out_size) {
    const float* X    = (const float*)d_in[0];
    const float* A    = (const float*)d_in[1];
    const int*   p    = (const int*)  d_in[2];
    const float* cW1  = (const float*)d_in[3];
    const float* cb1  = (const float*)d_in[4];
    const float* cW2  = (const float*)d_in[5];
    const float* cb2  = (const float*)d_in[6];
    const float* wmW1 = (const float*)d_in[7];
    const float* wmb1 = (const float*)d_in[8];
    const float* wmW2 = (const float*)d_in[9];
    const float* wmb2 = (const float*)d_in[10];
    const float* wmW3 = (const float*)d_in[11];
    const float* wmb3 = (const float*)d_in[12];
    const float* fW1  = (const float*)d_in[13];
    const float* fb1  = (const float*)d_in[14];
    const float* fW2  = (const float*)d_in[15];
    const float* fb2  = (const float*)d_in[16];
    const float* eps  = (const float*)d_in[17];
    const float* g0W1 = (const float*)d_in[18];
    const float* g0b1 = (const float*)d_in[19];
    const float* g0W2 = (const float*)d_in[20];
    const float* g0b2 = (const float*)d_in[21];
    const float* g1W1 = (const float*)d_in[22];
    const float* g1b1 = (const float*)d_in[23];
    const float* g1W2 = (const float*)d_in[24];
    const float* g1b2 = (const float*)d_in[25];
    const float* g2W1 = (const float*)d_in[26];
    const float* g2b1 = (const float*)d_in[27];
    const float* g2W2 = (const float*)d_in[28];
    const float* g2b2 = (const float*)d_in[29];
    const float* outW = (const float*)d_in[30];
    const float* outb = (const float*)d_in[31];
    float* dout = (float*)d_out;

    float *h0_p, *h1_p, *h2_p;
    unsigned *km1_p, *km2_p;
    cudaGetSymbolAddress((void**)&h0_p, g_h);
    h1_p = h0_p + BN*Hx;
    h2_p = h0_p + 2*BN*Hx;
    cudaGetSymbolAddress((void**)&km1_p, g_kmask1);
    cudaGetSymbolAddress((void**)&km2_p, g_kmask2);

    // dynamic smem limits (idempotent host-side calls)
    cudaFuncSetAttribute((const void*)node_mlps_tiled,
        cudaFuncAttributeMaxDynamicSharedMemorySize, 57600);
    cudaFuncSetAttribute((const void*)gin_kernel<128>,
        cudaFuncAttributeMaxDynamicSharedMemorySize, 73728);
    cudaFuncSetAttribute((const void*)gin_kernel<64>,
        cudaFuncAttributeMaxDynamicSharedMemorySize, 49152);

    adjmask_kernel<<<BN/8, 256>>>(A);
    node_mlps_tiled<<<dim3(BN/32, 5), 256, 57600>>>(X,
        cW1, cb1, cW2, cb2, fW1, fb1, fW2, fb2,
        wmW1, wmb1, wmW2, wmb2, wmW3, wmb3);
    prune_kernel<<<Bx, Nx>>>(p);
    curv_kernel<<<Bx, Nx>>>();

    gin_kernel<128><<<BN/32, 256, 73728>>>(X,    nullptr, eps, 0, g0W1, g0b1, g0W2, g0b2, h0_p);
    gin_kernel<64> <<<BN/32, 256, 49152>>>(h0_p, km1_p,   eps, 1, g1W1, g1b1, g1W2, g1b2, h1_p);
    gin_kernel<64> <<<BN/32, 256, 49152>>>(h1_p, km2_p,   eps, 2, g2W1, g2b1, g2W2, g2b2, h2_p);

    final_part_kernel<<<dim3(Bx, 8), 320>>>(X);
    final_out_kernel<<<Bx, 320>>>(outW, outb, dout, out_size);
}